// round 3
// baseline (speedup 1.0000x reference)
#include <cuda_runtime.h>
#include <math.h>
#include <stdint.h>

// Problem constants
#define BATCH 2
#define NPTS 1024
#define NUM_BINS 22
#define TDIM 16
#define MAX_DIST 40.0f
#define LN_EPS 1e-5f

// Table stored planar: plane k (k = d/4) holds, per bin, one float4 (d%4).
// plane size = 22 * 4 floats = 88 floats = 352 bytes.
#define PLANE_FLOATS (NUM_BINS * 4)
__device__ float g_table[4 * PLANE_FLOATS];

// ---------------------------------------------------------------------------
// Kernel 1: build the 22x16 table in planar layout. One warp, one thread/bin.
// ---------------------------------------------------------------------------
__global__ void build_table_kernel(const float* __restrict__ W,
                                   const float* __restrict__ b,
                                   const float* __restrict__ gamma,
                                   const float* __restrict__ beta) {
    int bin = threadIdx.x;
    if (bin >= NUM_BINS) return;

    float h[TDIM];
    float sum = 0.0f;
#pragma unroll
    for (int d = 0; d < TDIM; ++d) {
        h[d] = W[bin * TDIM + d] + b[d];
        sum += h[d];
    }
    float mu = sum * (1.0f / TDIM);
    float var = 0.0f;
#pragma unroll
    for (int d = 0; d < TDIM; ++d) {
        float c = h[d] - mu;
        var += c * c;
    }
    var *= (1.0f / TDIM);
    float inv = rsqrtf(var + LN_EPS);
#pragma unroll
    for (int d = 0; d < TDIM; ++d) {
        float v = (h[d] - mu) * inv * gamma[d] + beta[d];
        v = fmaxf(v, 0.0f);
        g_table[(d >> 2) * PLANE_FLOATS + bin * 4 + (d & 3)] = v;
    }
}

// ---------------------------------------------------------------------------
// Kernel 2: ONE block per i; covers both batches and all 1024 j's.
// Grid = 1024 blocks of 256 => ~1 wave on 148 SMs.
//   Phase A: thread t computes (table byte-offset, scale) for j = q*256+t,
//            packs into float2 in smem.
//   Phase B: 4 lanes/pair; one LDS.64 (off+s, broadcast in group),
//            one LDS.128 plane gather, 2 packed f32x2 muls, one STG.128.
// ---------------------------------------------------------------------------
__global__ __launch_bounds__(256)
void encode_kernel(const float* __restrict__ coords,
                   const float* __restrict__ conf,
                   float* __restrict__ out) {
    __shared__ float  sT[4 * PLANE_FLOATS];   // 1408 B
    __shared__ float2 sP[NPTS];               // 8 KB: (off_bytes, scale) per j

    const int tid = threadIdx.x;
    const int i   = blockIdx.x;

    for (int t = tid; t < 4 * PLANE_FLOATS; t += 256) sT[t] = g_table[t];

    const int   p = tid >> 2;                  // pair slot within 64
    const int   k = tid & 3;                   // which float4 of the 16-vec
    const char* tb = (const char*)sT + k * (PLANE_FLOATS * 4);
    const float inv_w = (float)(NUM_BINS - 1) / MAX_DIST;   // 21/40

    for (int batch = 0; batch < BATCH; ++batch) {
        // ---- Phase A: per-j precompute ----
        {
            const float* ci_ptr = coords + ((size_t)batch * NPTS + i) * 3;
            const float xi = ci_ptr[0], yi = ci_ptr[1], zi = ci_ptr[2];
            const float ci = conf[batch * NPTS + i];

#pragma unroll
            for (int q = 0; q < 4; ++q) {
                const int j = q * 256 + tid;
                const float* cj_ptr = coords + ((size_t)batch * NPTS + j) * 3;
                const float dx = xi - cj_ptr[0];
                const float dy = yi - cj_ptr[1];
                const float dz = zi - cj_ptr[2];
                const float cj = conf[batch * NPTS + j];

                const float dist =
                    sqrtf(fmaf(dx, dx, fmaf(dy, dy, fmaf(dz, dz, 1e-8f))));

                int bin;
                if (ci > 0.0f && cj > 0.0f) {
                    bin = (int)(dist * inv_w) + 1;       // #edges strictly < dist
                    bin = (bin > NUM_BINS - 2) ? (NUM_BINS - 2) : bin;
                } else {
                    bin = NUM_BINS - 1;
                }
                sP[j] = make_float2(__int_as_float(bin * 16),  // bytes in plane
                                    fminf(ci, cj));
            }
        }
        __syncthreads();

        // ---- Phase B: gather + scale + store (16 iters x 64 pairs) ----
        float* optr = out + (((size_t)batch * NPTS + i) * NPTS + p) * TDIM + k * 4;

#pragma unroll 4
        for (int it = 0; it < 16; ++it) {
            const float2 pk = sP[it * 64 + p];
            const int   off = __float_as_int(pk.x);
            const float s   = pk.y;

            float4 v = *(const float4*)(tb + off);

            uint64_t lo, hi, sv, rlo, rhi;
            asm("mov.b64 %0, {%1, %2};" : "=l"(sv) : "f"(s), "f"(s));
            asm("mov.b64 %0, {%1, %2};" : "=l"(lo) : "f"(v.x), "f"(v.y));
            asm("mov.b64 %0, {%1, %2};" : "=l"(hi) : "f"(v.z), "f"(v.w));
            asm("mul.rn.f32x2 %0, %1, %2;" : "=l"(rlo) : "l"(lo), "l"(sv));
            asm("mul.rn.f32x2 %0, %1, %2;" : "=l"(rhi) : "l"(hi), "l"(sv));
            float4 r;
            asm("mov.b64 {%0, %1}, %2;" : "=f"(r.x), "=f"(r.y) : "l"(rlo));
            asm("mov.b64 {%0, %1}, %2;" : "=f"(r.z), "=f"(r.w) : "l"(rhi));

            *(float4*)(optr + (size_t)it * 64 * TDIM) = r;
        }
        __syncthreads();   // protect sP before next batch overwrites it
    }
}

// ---------------------------------------------------------------------------
// Launch
// ---------------------------------------------------------------------------
extern "C" void kernel_launch(void* const* d_in, const int* in_sizes, int n_in,
                              void* d_out, int out_size) {
    const float* coords = (const float*)d_in[0];  // (B,N,3)
    const float* conf   = (const float*)d_in[1];  // (B,N)
    const float* W      = (const float*)d_in[2];  // (22,16)
    const float* b      = (const float*)d_in[3];  // (16,)
    const float* gamma  = (const float*)d_in[4];  // (16,)
    const float* beta   = (const float*)d_in[5];  // (16,)
    float* out = (float*)d_out;                   // (B,N,N,16)

    build_table_kernel<<<1, 32>>>(W, b, gamma, beta);

    encode_kernel<<<NPTS, 256>>>(coords, conf, out);
}